// round 5
// baseline (speedup 1.0000x reference)
#include <cuda_runtime.h>
#include <cstdint>

constexpr int Bc=4, Nn=2048, Dd=256, Hh=4;
constexpr int TI=64, TJ=32, NT=Nn/TJ;   // 64 tiles

__device__ float g_WhT [Bc*Dd*Nn];      // [b][c][j]
__device__ float g_esrc[Bc*Hh*Nn];
__device__ float g_edst[Bc*Hh*Nn];
__device__ float g_mx  [Bc*Hh*Nn];
__device__ float g_inv [Bc*Hh*Nn];

__device__ __forceinline__ float totf(float x){
    uint32_t u; asm("cvt.rna.tf32.f32 %0, %1;" : "=r"(u) : "f"(x));
    return __uint_as_float(u);
}
__device__ __forceinline__ void mma8(float* d, float4 a, float2 b){
    asm volatile("mma.sync.aligned.m16n8k8.row.col.f32.tf32.tf32.f32 "
        "{%0,%1,%2,%3}, {%4,%5,%6,%7}, {%8,%9}, {%0,%1,%2,%3};"
        : "+f"(d[0]), "+f"(d[1]), "+f"(d[2]), "+f"(d[3])
        : "r"(__float_as_uint(a.x)), "r"(__float_as_uint(a.y)),
          "r"(__float_as_uint(a.z)), "r"(__float_as_uint(a.w)),
          "r"(__float_as_uint(b.x)), "r"(__float_as_uint(b.y)));
}

// ---------------------------------------------------------------------------
// K1: Wh = h @ W, stored transposed into g_WhT[b][c][j]
// ---------------------------------------------------------------------------
__global__ __launch_bounds__(256)
void gemm_h_w(const float* __restrict__ A, const float* __restrict__ Bw){
    __shared__ float As[16][64];
    __shared__ float Bs[16][64];
    __shared__ float Tr[64][65];
    const int tid=threadIdx.x;
    const int m0=blockIdx.x*64, n0=blockIdx.y*64;
    const int tm=tid>>4, tn=tid&15;
    const int lm=tid>>2, lk=(tid&3)*4;
    const int lbk=tid>>4, lbn=(tid&15)*4;
    float acc[4][4];
#pragma unroll
    for(int r=0;r<4;r++)
#pragma unroll
        for(int c=0;c<4;c++) acc[r][c]=0.f;
    for(int k0=0;k0<256;k0+=16){
        float4 av = *(const float4*)(A + (size_t)(m0+lm)*256 + k0+lk);
        As[lk+0][lm]=av.x; As[lk+1][lm]=av.y; As[lk+2][lm]=av.z; As[lk+3][lm]=av.w;
        *(float4*)&Bs[lbk][lbn] = *(const float4*)(Bw + (size_t)(k0+lbk)*256 + n0+lbn);
        __syncthreads();
#pragma unroll
        for(int k=0;k<16;k++){
            float4 a4=*(const float4*)&As[k][tm*4];
            float4 b4=*(const float4*)&Bs[k][tn*4];
            float ar[4]={a4.x,a4.y,a4.z,a4.w}, br[4]={b4.x,b4.y,b4.z,b4.w};
#pragma unroll
            for(int r=0;r<4;r++)
#pragma unroll
                for(int c=0;c<4;c++) acc[r][c]+=ar[r]*br[c];
        }
        __syncthreads();
    }
#pragma unroll
    for(int r=0;r<4;r++)
#pragma unroll
        for(int c=0;c<4;c++) Tr[tn*4+c][tm*4+r]=acc[r][c];
    __syncthreads();
    const int b = m0>>11, ml = m0&2047;
    const int n = tid>>2, ms = (tid&3)*16;
    float* dst = g_WhT + ((size_t)(b*Dd + n0 + n))*Nn + ml + ms;
#pragma unroll
    for(int k=0;k<4;k++)
        *(float4*)(dst + k*4) = make_float4(Tr[n][ms+k*4], Tr[n][ms+k*4+1],
                                            Tr[n][ms+k*4+2], Tr[n][ms+k*4+3]);
}

// ---------------------------------------------------------------------------
// K2: e_src/e_dst from WhT (coalesced over n)
// ---------------------------------------------------------------------------
__global__ __launch_bounds__(128)
void gat_attn_proj(const float* __restrict__ a_src, const float* __restrict__ a_dst){
    __shared__ float sa[64], sd[64];
    const int tid=threadIdx.x;
    const int chunk=blockIdx.x&15, h=(blockIdx.x>>4)&3, b=blockIdx.x>>6;
    if(tid<64){ sa[tid]=a_src[h*64+tid]; sd[tid]=a_dst[h*64+tid]; }
    __syncthreads();
    const int n = chunk*128 + tid;
    const float* wp = g_WhT + ((size_t)(b*Dd + h*64))*Nn + n;
    float ss=0.f, ds=0.f;
#pragma unroll 8
    for(int d=0; d<64; d++){
        float w = wp[(size_t)d*Nn];
        ss += w*sa[d]; ds += w*sd[d];
    }
    int g = (b*Hh+h)*Nn + n;
    g_esrc[g]=ss; g_edst[g]=ds;
}

// ---------------------------------------------------------------------------
// K3: per-row softmax stats (max, 1/sum) for all 4 heads
// ---------------------------------------------------------------------------
__global__ __launch_bounds__(256)
void gat_stats(const int* __restrict__ adj){
    const int b=blockIdx.x>>11, i=blockIdx.x&(Nn-1);
    const int tid=threadIdx.x, lane=tid&31, warp=tid>>5;
    float es[4];
#pragma unroll
    for(int h=0;h<4;h++) es[h]=g_esrc[(b*Hh+h)*Nn+i];
    float ev[8][4], m[4]={-1e30f,-1e30f,-1e30f,-1e30f};
    const size_t arow=(size_t)(b*Nn+i)*Nn;
#pragma unroll
    for(int k=0;k<8;k++){
        int j=tid+k*256; int a=adj[arow+j];
#pragma unroll
        for(int h=0;h<4;h++){
            float e=es[h]+g_edst[(b*Hh+h)*Nn+j];
            e=(e>0.f)?e:0.2f*e; e=a?e:-1e30f;
            ev[k][h]=e; m[h]=fmaxf(m[h],e);
        }
    }
    __shared__ float sred[4][8]; __shared__ float sfin[4];
#pragma unroll
    for(int h=0;h<4;h++)
#pragma unroll
        for(int o=16;o;o>>=1) m[h]=fmaxf(m[h],__shfl_xor_sync(0xffffffffu,m[h],o));
    if(lane==0)
#pragma unroll
        for(int h=0;h<4;h++) sred[h][warp]=m[h];
    __syncthreads();
    if(tid==0){
#pragma unroll
        for(int h=0;h<4;h++){
            float mm=sred[h][0];
#pragma unroll
            for(int w2=1;w2<8;w2++) mm=fmaxf(mm,sred[h][w2]);
            sfin[h]=mm;
        }
    }
    __syncthreads();
    float M[4];
#pragma unroll
    for(int h=0;h<4;h++) M[h]=sfin[h];
    float s[4]={0.f,0.f,0.f,0.f};
#pragma unroll
    for(int k=0;k<8;k++)
#pragma unroll
        for(int h=0;h<4;h++) s[h]+=__expf(ev[k][h]-M[h]);
#pragma unroll
    for(int h=0;h<4;h++)
#pragma unroll
        for(int o=16;o;o>>=1) s[h]+=__shfl_xor_sync(0xffffffffu,s[h],o);
    __syncthreads();
    if(lane==0)
#pragma unroll
        for(int h=0;h<4;h++) sred[h][warp]=s[h];
    __syncthreads();
    if(tid<4){
        int h=tid; float S=0.f;
#pragma unroll
        for(int w2=0;w2<8;w2++) S+=sred[h][w2];
        int g=(b*Hh+h)*Nn+i;
        g_mx[g]=M[h]; g_inv[g]=(M[h]>-1e29f)?(1.f/S):0.f;
    }
}

// ---------------------------------------------------------------------------
// K4: fused alpha + HMMA tf32 (mma.sync m16n8k8).
// Block: 256 thr, TI=64 rows, all j. A/B staged in fragment layout.
//   A_s: 64 frags (h,mb,kb) x 32 lanes x float4  (32KB)
//   B_s: 128 frags (kb,nb)  x 33 lanes x float2  (33KB, padded)
// Warp w: head h=w>>1, col-half nh=w&1 -> M=64,N=32 accum (64 regs).
// ---------------------------------------------------------------------------
constexpr int OFF_B  = 32768;
constexpr int OFF_ES = OFF_B + 128*33*8;     // 66560
constexpr int SMEM_MAIN = OFF_ES + 3*256*4;  // 69632

__global__ __launch_bounds__(256, 1)
void gat_main(const int* __restrict__ adj, float* __restrict__ h_out,
              float* __restrict__ alpha_out, int write_alpha)
{
    extern __shared__ char smem[];
    float4* As  = (float4*)smem;
    float2* Bs2 = (float2*)(smem + OFF_B);
    float* es = (float*)(smem + OFF_ES);
    float* mx = es + 256;
    float* iv = mx + 256;

    const int tid  = threadIdx.x;
    const int lane = tid & 31;
    const int b  = blockIdx.x >> 5;
    const int i0 = (blockIdx.x & 31) * TI;

    {   // es/mx/iv stage: h=tid>>6, i=tid&63 -> index h*64+i == tid
        int g = (b*Hh + (tid>>6))*Nn + i0 + (tid&63);
        es[tid] = g_esrc[g]; mx[tid] = g_mx[g]; iv[tid] = g_inv[g];
    }
    __syncthreads();

    // ---- alpha-task constants (2 tasks: T=tid, T=tid+256) ----
    int th[2], tmb[2], tkb[2], tr[2];
    const int* adjA[2]; const int* adjB[2];
#pragma unroll
    for(int k=0;k<2;k++){
        int T = tid + k*256;
        th[k]=T>>7; tmb[k]=(T>>5)&3; tkb[k]=(T>>3)&3; tr[k]=T&7;
        int iA = tmb[k]*16 + tr[k];
        adjA[k] = adj + ((size_t)(b*Nn + i0 + iA))*Nn + tkb[k]*8;
        adjB[k] = adjA[k] + (size_t)8*Nn;
    }
    const float* whrow = g_WhT + ((size_t)(b*Dd + tid))*Nn;

    // ---- MMA mapping ----
    const int wid = tid>>5, h_w = wid>>1, nh = wid&1;

    float acc[4][4][4];
#pragma unroll
    for(int m2=0;m2<4;m2++)
#pragma unroll
        for(int n2=0;n2<4;n2++)
#pragma unroll
            for(int q=0;q<4;q++) acc[m2][n2][q]=0.f;

    int4   adjp[2][4];
    float4 Bp[8];

    // prefetch tile 0
#pragma unroll
    for(int k=0;k<2;k++){
        adjp[k][0]=((const int4*)adjA[k])[0]; adjp[k][1]=((const int4*)adjA[k])[1];
        adjp[k][2]=((const int4*)adjB[k])[0]; adjp[k][3]=((const int4*)adjB[k])[1];
    }
#pragma unroll
    for(int r=0;r<8;r++) Bp[r] = ((const float4*)whrow)[r];

    for(int t=0; t<NT; t++){
        const int j0 = t*TJ;

        // ---- phase W: alpha gen -> A_s + gmem; B regs -> B_s ----
#pragma unroll
        for(int k=0;k<2;k++){
            const int h=th[k], mb=tmb[k], kb=tkb[k], r=tr[k];
            const int iA = mb*16 + r;
            const float esA=es[h*64+iA],   mxA=mx[h*64+iA],   ivA=iv[h*64+iA];
            const float esB=es[h*64+iA+8], mxB=mx[h*64+iA+8], ivB=iv[h*64+iA+8];
            const float* edp = g_edst + (size_t)(b*Hh+h)*Nn + j0 + kb*8;
            float4 e0 = *(const float4*)edp;
            float4 e1 = *(const float4*)(edp+4);
            float ed[8]={e0.x,e0.y,e0.z,e0.w,e1.x,e1.y,e1.z,e1.w};
            int mA[8]={adjp[k][0].x,adjp[k][0].y,adjp[k][0].z,adjp[k][0].w,
                       adjp[k][1].x,adjp[k][1].y,adjp[k][1].z,adjp[k][1].w};
            int mB[8]={adjp[k][2].x,adjp[k][2].y,adjp[k][2].z,adjp[k][2].w,
                       adjp[k][3].x,adjp[k][3].y,adjp[k][3].z,adjp[k][3].w};
            float uA[8], uB[8];
#pragma unroll
            for(int jj=0;jj<8;jj++){
                float eA = esA + ed[jj]; eA = (eA>0.f)?eA:0.2f*eA;
                uA[jj] = mA[jj] ? __expf(eA-mxA)*ivA : 0.f;
                float eB = esB + ed[jj]; eB = (eB>0.f)?eB:0.2f*eB;
                uB[jj] = mB[jj] ? __expf(eB-mxB)*ivB : 0.f;
            }
            if(write_alpha){
                float* pa = alpha_out + ((size_t)((b*Hh+h)*Nn) + i0+iA)*Nn + j0 + kb*8;
                *(float4*)pa     = make_float4(uA[0],uA[1],uA[2],uA[3]);
                *(float4*)(pa+4) = make_float4(uA[4],uA[5],uA[6],uA[7]);
                float* pb = pa + (size_t)8*Nn;
                *(float4*)pb     = make_float4(uB[0],uB[1],uB[2],uB[3]);
                *(float4*)(pb+4) = make_float4(uB[4],uB[5],uB[6],uB[7]);
            }
            const int fi = (h*16 + mb*4 + kb)*32 + r*4;
#pragma unroll
            for(int c=0;c<4;c++)
                As[fi + c] = make_float4(totf(uA[c]), totf(uB[c]),
                                         totf(uA[c+4]), totf(uB[c+4]));
        }
        {   // B stage: c = tid; frag (kb, nb=c>>3), lane (c&7)*4+rr
            float wv[32];
#pragma unroll
            for(int r=0;r<8;r++){ wv[r*4]=Bp[r].x; wv[r*4+1]=Bp[r].y;
                                  wv[r*4+2]=Bp[r].z; wv[r*4+3]=Bp[r].w; }
            const int nb = tid>>3, lbase = (tid&7)*4;
#pragma unroll
            for(int kb=0;kb<4;kb++)
#pragma unroll
                for(int rr=0;rr<4;rr++)
                    Bs2[(kb*32+nb)*33 + lbase + rr] =
                        make_float2(totf(wv[kb*8+rr]), totf(wv[kb*8+rr+4]));
        }
        __syncthreads();

        // ---- prefetch t+1 ----
        if(t+1 < NT){
            const int jn = (t+1)*TJ;
#pragma unroll
            for(int k=0;k<2;k++){
                adjp[k][0]=((const int4*)(adjA[k]+jn))[0];
                adjp[k][1]=((const int4*)(adjA[k]+jn))[1];
                adjp[k][2]=((const int4*)(adjB[k]+jn))[0];
                adjp[k][3]=((const int4*)(adjB[k]+jn))[1];
            }
#pragma unroll
            for(int r=0;r<8;r++) Bp[r] = ((const float4*)(whrow+jn))[r];
        }

        // ---- MMA on tile t ----
#pragma unroll
        for(int kb=0;kb<4;kb++){
            float4 av[4]; float2 bv[4];
#pragma unroll
            for(int m2=0;m2<4;m2++)
                av[m2] = As[(h_w*16 + m2*4 + kb)*32 + lane];
#pragma unroll
            for(int n2=0;n2<4;n2++)
                bv[n2] = Bs2[(kb*32 + h_w*8 + nh*4 + n2)*33 + lane];
#pragma unroll
            for(int m2=0;m2<4;m2++)
#pragma unroll
                for(int n2=0;n2<4;n2++)
                    mma8(acc[m2][n2], av[m2], bv[n2]);
        }
        __syncthreads();
    }

    // ---- epilogue: write h_out ----
    const int cb = h_w*64 + nh*32;
    const int rl = lane>>2, cl = (lane&3)*2;
#pragma unroll
    for(int m2=0;m2<4;m2++){
        float* p0 = h_out + ((size_t)(b*Nn) + i0 + m2*16 + rl)*Dd + cb + cl;
        float* p1 = p0 + (size_t)8*Dd;
#pragma unroll
        for(int n2=0;n2<4;n2++){
            *(float2*)(p0 + n2*8) = make_float2(acc[m2][n2][0], acc[m2][n2][1]);
            *(float2*)(p1 + n2*8) = make_float2(acc[m2][n2][2], acc[m2][n2][3]);
        }
    }
}

// ---------------------------------------------------------------------------
extern "C" void kernel_launch(void* const* d_in, const int* in_sizes, int n_in,
                              void* d_out, int out_size){
    const float* h     = (const float*)d_in[0];
    const int*   adj   = (const int*)d_in[1];
    const float* W     = (const float*)d_in[2];
    const float* a_src = (const float*)d_in[3];
    const float* a_dst = (const float*)d_in[4];
    float* out = (float*)d_out;

    const long long houtN  = (long long)Bc*Nn*Dd;
    const long long alphaN = (long long)Bc*Hh*Nn*Nn;
    int write_alpha = ((long long)out_size >= houtN + alphaN) ? 1 : 0;
    float* alpha_out = out + houtN;

    cudaFuncSetAttribute(gat_main, cudaFuncAttributeMaxDynamicSharedMemorySize,
                         SMEM_MAIN);

    gemm_h_w<<<dim3(128,4),256>>>(h, W);
    gat_attn_proj<<<Bc*Hh*16,128>>>(a_src, a_dst);
    gat_stats<<<Bc*Nn,256>>>(adj);
    gat_main<<<Bc*32,256,SMEM_MAIN>>>(adj, out, alpha_out, write_alpha);
}